// round 7
// baseline (speedup 1.0000x reference)
#include <cuda_runtime.h>
#include <cuda_fp16.h>
#include <cstdint>
#include <cstddef>

#define NN   100000
#define EE   1600000
#define DINC 128
#define DHC  128
#define DOUTC 64

// ---------------- scratch (no allocations allowed) ----------------
__device__ int   g_deg[NN];
__device__ float g_dinv[NN];
__device__ int   g_rowptr[NN + 1];
__device__ int   g_cursor[NN];
__device__ int   g_col[EE];      // src node per CSR slot (grouped by dst)
__device__ float g_wgt[EE];      // dinv[src]*dinv[dst] per slot
__device__ float g_bufA[(size_t)NN * DHC];
__device__ float g_bufB[(size_t)NN * DHC];

#define SCAN_TPB 1024
#define SCAN_NBLK ((NN + SCAN_TPB - 1) / SCAN_TPB)   // 98
__device__ int g_bsum[128];

// ---------------- graph build ----------------
__global__ void count_deg_kernel(const int* __restrict__ dst) {
    int e = blockIdx.x * blockDim.x + threadIdx.x;
    if (e < EE) atomicAdd(&g_deg[dst[e]], 1);
}

// per-block local exclusive scan of edge-indegree + block totals + dinv
__global__ void scan_local_kernel() {
    __shared__ int ws[32];
    int tid  = threadIdx.x;
    int lane = tid & 31;
    int wid  = tid >> 5;
    int i = blockIdx.x * SCAN_TPB + tid;
    int v = (i < NN) ? g_deg[i] : 0;
    if (i < NN) g_dinv[i] = rsqrtf((float)(v + 1));   // +1 self loop
    int x = v;
    #pragma unroll
    for (int o = 1; o < 32; o <<= 1) {
        int y = __shfl_up_sync(0xFFFFFFFFu, x, o);
        if (lane >= o) x += y;
    }
    if (lane == 31) ws[wid] = x;
    __syncthreads();
    if (wid == 0) {
        int s = ws[lane];
        #pragma unroll
        for (int o = 1; o < 32; o <<= 1) {
            int y = __shfl_up_sync(0xFFFFFFFFu, s, o);
            if (lane >= o) s += y;
        }
        ws[lane] = s;
    }
    __syncthreads();
    int excl = (wid ? ws[wid - 1] : 0) + x - v;
    if (i < NN) g_rowptr[i] = excl;
    if (tid == 0) g_bsum[blockIdx.x] = ws[31];
}

__global__ void scan_block_kernel() {   // 1 block, 128 threads >= 98 partials
    __shared__ int wsum[4];
    int t = threadIdx.x, lane = t & 31, wid = t >> 5;
    int v = (t < SCAN_NBLK) ? g_bsum[t] : 0;
    int x = v;
    #pragma unroll
    for (int o = 1; o < 32; o <<= 1) {
        int y = __shfl_up_sync(0xFFFFFFFFu, x, o);
        if (lane >= o) x += y;
    }
    if (lane == 31) wsum[wid] = x;
    __syncthreads();
    if (t == 0) {
        int a = 0;
        #pragma unroll
        for (int k = 0; k < 4; k++) { int s = wsum[k]; wsum[k] = a; a += s; }
    }
    __syncthreads();
    int excl = wsum[wid] + x - v;
    if (t < SCAN_NBLK) g_bsum[t] = excl;
}

__global__ void scan_add_kernel() {
    int i = blockIdx.x * blockDim.x + threadIdx.x;
    if (i < NN) {
        int r = g_rowptr[i] + g_bsum[i >> 10];
        g_rowptr[i] = r;
        g_cursor[i] = r;
    }
    if (i == 0) g_rowptr[NN] = EE;
}

__global__ void fill_csr_kernel(const int* __restrict__ src, const int* __restrict__ dst) {
    int e = blockIdx.x * blockDim.x + threadIdx.x;
    if (e < EE) {
        int s = src[e], d = dst[e];
        int slot = atomicAdd(&g_cursor[d], 1);
        g_col[slot] = s;
        g_wgt[slot] = g_dinv[s] * g_dinv[d];
    }
}

// ================= fp16-split mma.sync GEMM =================
// C[N,BN] = A[N,128] @ W[128,BN], fp32-grade: x = hi + lo (fp16 each),
// D = Ah*Bh + Ah*Bl + Al*Bh accumulated in fp32 by HMMA.16816.
__device__ __forceinline__ uint32_t s2u(const void* p) {
    uint32_t a;
    asm("{ .reg .u64 t; cvta.to.shared.u64 t, %1; cvt.u32.u64 %0, t; }" : "=r"(a) : "l"(p));
    return a;
}

#define LDSM4(r, a)                                                            \
    asm volatile("ldmatrix.sync.aligned.m8n8.x4.shared.b16 {%0,%1,%2,%3}, [%4];" \
                 : "=r"((r)[0]), "=r"((r)[1]), "=r"((r)[2]), "=r"((r)[3])      \
                 : "r"(a))

__device__ __forceinline__ void mma16816(float* c, const uint32_t* a, const uint32_t* b) {
    asm volatile(
        "mma.sync.aligned.m16n8k16.row.col.f32.f16.f16.f32 "
        "{%0,%1,%2,%3}, {%4,%5,%6,%7}, {%8,%9}, {%0,%1,%2,%3};"
        : "+f"(c[0]), "+f"(c[1]), "+f"(c[2]), "+f"(c[3])
        : "r"(a[0]), "r"(a[1]), "r"(a[2]), "r"(a[3]), "r"(b[0]), "r"(b[1]));
}

__device__ __forceinline__ uint32_t pack2(__half a, __half b) {
    __half2 h = __halves2half2(a, b);
    return *(uint32_t*)&h;
}

// smem tile: rows of KC=64 fp16 + 8 pad halves (row stride 72 halves = 144 B)
template <int BN>
__global__ void __launch_bounds__(256, 2)
gemm_mma_kernel(const float* __restrict__ A, const float* __restrict__ W,
                float* __restrict__ C) {
    constexpr int K = 128, KC = 64, RS = 72;
    constexpr int A_HI = 0;
    constexpr int A_LO = 128 * RS;
    constexpr int B_HI = 2 * 128 * RS;
    constexpr int B_LO = B_HI + BN * RS;
    constexpr int NT = BN / 16;          // n8-tiles per warp (8 or 4)
    constexpr int NP = NT / 2;           // ldmatrix x4 pairs (4 or 2)

    extern __shared__ __half sm[];
    const uint32_t sb = s2u(sm);
    const int tid  = threadIdx.x;
    const int lane = tid & 31;
    const int warp = tid >> 5;
    const int wm = (warp & 3) * 32;
    const int wn = (warp >> 2) * (BN / 2);
    const int rowBase = blockIdx.x * 128;

    float acc[2][NT][4];
    #pragma unroll
    for (int mt = 0; mt < 2; mt++)
        #pragma unroll
        for (int nt = 0; nt < NT; nt++)
            #pragma unroll
            for (int q = 0; q < 4; q++) acc[mt][nt][q] = 0.0f;

    // ldmatrix lane->address maps
    const int aRow = (lane & 7) + ((lane >> 3) & 1) * 8;   // A: r0 rows0-7@k0, r1 rows8-15@k0, r2 rows0-7@k8, r3 rows8-15@k8
    const int aK   = (lane >> 4) * 8;
    const int bN   = (lane & 7) + ((lane >> 4) << 3);      // B: r0 n0-7@k0, r1 n0-7@k8, r2 n8-15@k0, r3 n8-15@k8
    const int bK   = ((lane >> 3) & 1) * 8;

    for (int kc = 0; kc < 2; kc++) {
        // ---- stage A chunk (128 x 64 fp32 -> hi/lo fp16) ----
        #pragma unroll
        for (int l = 0; l < 8; l++) {
            int i = tid + l * 256;           // 2048 float4
            int r = i >> 4;
            int c = (i & 15) * 4;
            float4 v = make_float4(0.f, 0.f, 0.f, 0.f);
            int gr = rowBase + r;
            if (gr < NN) v = *(const float4*)(A + (size_t)gr * K + kc * KC + c);
            __half h0 = __float2half_rn(v.x), h1 = __float2half_rn(v.y);
            __half h2 = __float2half_rn(v.z), h3 = __float2half_rn(v.w);
            __half q0 = __float2half_rn(v.x - __half2float(h0));
            __half q1 = __float2half_rn(v.y - __half2float(h1));
            __half q2 = __float2half_rn(v.z - __half2float(h2));
            __half q3 = __float2half_rn(v.w - __half2float(h3));
            *(uint2*)&sm[A_HI + r * RS + c] = make_uint2(pack2(h0, h1), pack2(h2, h3));
            *(uint2*)&sm[A_LO + r * RS + c] = make_uint2(pack2(q0, q1), pack2(q2, q3));
        }
        // ---- stage B chunk: Bsm[n][k] = W[kc*64+k][n], k0..k0+3 per thread ----
        #pragma unroll
        for (int l = 0; l < BN * KC / 4 / 256; l++) {
            int i  = tid + l * 256;
            int n  = i % BN;                  // consecutive tid -> consecutive n (coalesced)
            int k0 = (i / BN) * 4;
            float v0 = W[(size_t)(kc * KC + k0 + 0) * BN + n];
            float v1 = W[(size_t)(kc * KC + k0 + 1) * BN + n];
            float v2 = W[(size_t)(kc * KC + k0 + 2) * BN + n];
            float v3 = W[(size_t)(kc * KC + k0 + 3) * BN + n];
            __half h0 = __float2half_rn(v0), h1 = __float2half_rn(v1);
            __half h2 = __float2half_rn(v2), h3 = __float2half_rn(v3);
            __half q0 = __float2half_rn(v0 - __half2float(h0));
            __half q1 = __float2half_rn(v1 - __half2float(h1));
            __half q2 = __float2half_rn(v2 - __half2float(h2));
            __half q3 = __float2half_rn(v3 - __half2float(h3));
            *(uint2*)&sm[B_HI + n * RS + k0] = make_uint2(pack2(h0, h1), pack2(h2, h3));
            *(uint2*)&sm[B_LO + n * RS + k0] = make_uint2(pack2(q0, q1), pack2(q2, q3));
        }
        __syncthreads();

        #pragma unroll
        for (int ks = 0; ks < KC / 16; ks++) {
            uint32_t ah[2][4], al[2][4];
            #pragma unroll
            for (int mt = 0; mt < 2; mt++) {
                uint32_t off = (uint32_t)((wm + mt * 16 + aRow) * RS + ks * 16 + aK) * 2;
                LDSM4(ah[mt], sb + A_HI * 2 + off);
                LDSM4(al[mt], sb + A_LO * 2 + off);
            }
            #pragma unroll
            for (int np = 0; np < NP; np++) {
                uint32_t bh[4], bl[4];
                uint32_t off = (uint32_t)((wn + np * 16 + bN) * RS + ks * 16 + bK) * 2;
                LDSM4(bh, sb + B_HI * 2 + off);
                LDSM4(bl, sb + B_LO * 2 + off);
                #pragma unroll
                for (int mt = 0; mt < 2; mt++) {
                    mma16816(acc[mt][np * 2 + 0], ah[mt], &bh[0]);
                    mma16816(acc[mt][np * 2 + 0], ah[mt], &bl[0]);
                    mma16816(acc[mt][np * 2 + 0], al[mt], &bh[0]);
                    mma16816(acc[mt][np * 2 + 1], ah[mt], &bh[2]);
                    mma16816(acc[mt][np * 2 + 1], ah[mt], &bl[2]);
                    mma16816(acc[mt][np * 2 + 1], al[mt], &bh[2]);
                }
            }
        }
        __syncthreads();
    }

    // epilogue: c0,c1 -> (row g, col tg*2..+1); c2,c3 -> (row g+8)
    const int g  = lane >> 2;
    const int tg = lane & 3;
    #pragma unroll
    for (int mt = 0; mt < 2; mt++) {
        int r0 = rowBase + wm + mt * 16 + g;
        #pragma unroll
        for (int nt = 0; nt < NT; nt++) {
            int col = wn + nt * 8 + tg * 2;
            if (r0 < NN)
                *(float2*)(C + (size_t)r0 * BN + col) = make_float2(acc[mt][nt][0], acc[mt][nt][1]);
            if (r0 + 8 < NN)
                *(float2*)(C + (size_t)(r0 + 8) * BN + col) = make_float2(acc[mt][nt][2], acc[mt][nt][3]);
        }
    }
}

// ---------------- Aggregation: warp per destination node (gather) ----------------
template <int D, bool RELU>
__global__ void agg_kernel(const float* __restrict__ hW,
                           const float* __restrict__ bias,
                           float* __restrict__ out) {
    constexpr int V = D / 32;                 // floats per lane (4 or 2)
    int gw   = (blockIdx.x * blockDim.x + threadIdx.x) >> 5;
    int lane = threadIdx.x & 31;
    if (gw >= NN) return;

    float di = g_dinv[gw];
    float acc[V];
    {   // self loop: weight = dinv^2
        float w = di * di;
        const float* p = hW + (size_t)gw * D + lane * V;
        if (V == 4) {
            float4 r = *(const float4*)p;
            acc[0] = w * r.x; acc[1] = w * r.y; acc[2] = w * r.z; acc[3] = w * r.w;
        } else {
            float2 r = *(const float2*)p;
            acc[0] = w * r.x; acc[1] = w * r.y;
        }
    }
    int j   = g_rowptr[gw];
    int end = g_rowptr[gw + 1];
    for (; j + 2 <= end; j += 2) {
        int   s0 = g_col[j],   s1 = g_col[j + 1];
        float w0 = g_wgt[j],   w1 = g_wgt[j + 1];
        if (V == 4) {
            float4 r0 = *(const float4*)(hW + (size_t)s0 * D + lane * 4);
            float4 r1 = *(const float4*)(hW + (size_t)s1 * D + lane * 4);
            acc[0] += w0 * r0.x; acc[1] += w0 * r0.y; acc[2] += w0 * r0.z; acc[3] += w0 * r0.w;
            acc[0] += w1 * r1.x; acc[1] += w1 * r1.y; acc[2] += w1 * r1.z; acc[3] += w1 * r1.w;
        } else {
            float2 r0 = *(const float2*)(hW + (size_t)s0 * D + lane * 2);
            float2 r1 = *(const float2*)(hW + (size_t)s1 * D + lane * 2);
            acc[0] += w0 * r0.x; acc[1] += w0 * r0.y;
            acc[0] += w1 * r1.x; acc[1] += w1 * r1.y;
        }
    }
    if (j < end) {
        int   s = g_col[j];
        float w = g_wgt[j];
        if (V == 4) {
            float4 r = *(const float4*)(hW + (size_t)s * D + lane * 4);
            acc[0] += w * r.x; acc[1] += w * r.y; acc[2] += w * r.z; acc[3] += w * r.w;
        } else {
            float2 r = *(const float2*)(hW + (size_t)s * D + lane * 2);
            acc[0] += w * r.x; acc[1] += w * r.y;
        }
    }
    float* po = out + (size_t)gw * D + lane * V;
    if (V == 4) {
        float4 b = *(const float4*)(bias + lane * 4);
        float4 o;
        o.x = acc[0] + b.x; o.y = acc[1] + b.y; o.z = acc[2] + b.z; o.w = acc[3] + b.w;
        if (RELU) {
            o.x = fmaxf(o.x, 0.f); o.y = fmaxf(o.y, 0.f);
            o.z = fmaxf(o.z, 0.f); o.w = fmaxf(o.w, 0.f);
        }
        *(float4*)po = o;
    } else {
        float2 b = *(const float2*)(bias + lane * 2);
        float2 o;
        o.x = acc[0] + b.x; o.y = acc[1] + b.y;
        if (RELU) { o.x = fmaxf(o.x, 0.f); o.y = fmaxf(o.y, 0.f); }
        *(float2*)po = o;
    }
}

// ---------------- launch ----------------
extern "C" void kernel_launch(void* const* d_in, const int* in_sizes, int n_in,
                              void* d_out, int out_size) {
    const float* x  = (const float*)d_in[0];
    const float* W0 = (const float*)d_in[1];
    const float* b0 = (const float*)d_in[2];
    const float* W1 = (const float*)d_in[3];
    const float* b1 = (const float*)d_in[4];
    const float* W2 = (const float*)d_in[5];
    const float* b2 = (const float*)d_in[6];
    const int*  src = (const int*)d_in[7];
    const int*  dst = (const int*)d_in[8];
    float* out = (float*)d_out;

    float *bufA = nullptr, *bufB = nullptr;
    void* degp = nullptr;
    cudaGetSymbolAddress((void**)&bufA, g_bufA);
    cudaGetSymbolAddress((void**)&bufB, g_bufB);
    cudaGetSymbolAddress(&degp, g_deg);

    // smem: (2*128 + 2*BN) rows * 72 halves * 2B
    const int SMEM128 = (2 * 128 + 2 * 128) * 72 * 2;   // 73728
    const int SMEM64  = (2 * 128 + 2 * 64)  * 72 * 2;   // 55296
    cudaFuncSetAttribute(gemm_mma_kernel<128>,
                         cudaFuncAttributeMaxDynamicSharedMemorySize, SMEM128);
    cudaFuncSetAttribute(gemm_mma_kernel<64>,
                         cudaFuncAttributeMaxDynamicSharedMemorySize, SMEM64);

    const int TPB = 256;
    const int edgeBlocks = (EE + TPB - 1) / TPB;
    const int gemmBlocks = (NN + 127) / 128;
    const int aggBlocks  = (NN * 32 + TPB - 1) / TPB;  // warp per node

    // build normalized CSR
    cudaMemsetAsync(degp, 0, NN * sizeof(int));
    count_deg_kernel<<<edgeBlocks, TPB>>>(dst);
    scan_local_kernel<<<SCAN_NBLK, SCAN_TPB>>>();
    scan_block_kernel<<<1, 128>>>();
    scan_add_kernel<<<(NN + 1023) / 1024, 1024>>>();
    fill_csr_kernel<<<edgeBlocks, TPB>>>(src, dst);

    // layer 0: relu(agg(x@W0) + b0)
    gemm_mma_kernel<128><<<gemmBlocks, TPB, SMEM128>>>(x, W0, bufA);
    agg_kernel<128, true><<<aggBlocks, TPB>>>(bufA, b0, bufB);
    // layer 1
    gemm_mma_kernel<128><<<gemmBlocks, TPB, SMEM128>>>(bufB, W1, bufA);
    agg_kernel<128, true><<<aggBlocks, TPB>>>(bufA, b1, bufB);
    // layer 2 (no relu) -> d_out
    gemm_mma_kernel<64><<<gemmBlocks, TPB, SMEM64>>>(bufB, W2, bufA);
    agg_kernel<64, false><<<aggBlocks, TPB>>>(bufA, b2, out);
}

// round 8
// speedup vs baseline: 1.0657x; 1.0657x over previous
#include <cuda_runtime.h>
#include <cuda_fp16.h>
#include <cstdint>
#include <cstddef>

#define NN   100000
#define EE   1600000
#define DINC 128
#define DHC  128
#define DOUTC 64

// ---------------- scratch (no allocations allowed) ----------------
__device__ int   g_deg[NN];
__device__ float g_dinv[NN];
__device__ int   g_rowptr[NN + 1];
__device__ int   g_cursor[NN];
__device__ int2  g_edge[EE];     // {src, wgt-bits} per CSR slot (grouped by dst)
__device__ float g_bufA[(size_t)NN * DHC];
__device__ float g_bufB[(size_t)NN * DHC];

#define SCAN_TPB 1024
#define SCAN_NBLK ((NN + SCAN_TPB - 1) / SCAN_TPB)   // 98
__device__ int g_bsum[128];

// ---------------- graph build ----------------
__global__ void count_deg_kernel(const int* __restrict__ dst) {
    int e = blockIdx.x * blockDim.x + threadIdx.x;
    if (e < EE) atomicAdd(&g_deg[dst[e]], 1);
}

// per-block local exclusive scan of edge-indegree + block totals + dinv
__global__ void scan_local_kernel() {
    __shared__ int ws[32];
    int tid  = threadIdx.x;
    int lane = tid & 31;
    int wid  = tid >> 5;
    int i = blockIdx.x * SCAN_TPB + tid;
    int v = (i < NN) ? g_deg[i] : 0;
    if (i < NN) g_dinv[i] = rsqrtf((float)(v + 1));   // +1 self loop
    int x = v;
    #pragma unroll
    for (int o = 1; o < 32; o <<= 1) {
        int y = __shfl_up_sync(0xFFFFFFFFu, x, o);
        if (lane >= o) x += y;
    }
    if (lane == 31) ws[wid] = x;
    __syncthreads();
    if (wid == 0) {
        int s = ws[lane];
        #pragma unroll
        for (int o = 1; o < 32; o <<= 1) {
            int y = __shfl_up_sync(0xFFFFFFFFu, s, o);
            if (lane >= o) s += y;
        }
        ws[lane] = s;
    }
    __syncthreads();
    int excl = (wid ? ws[wid - 1] : 0) + x - v;
    if (i < NN) g_rowptr[i] = excl;
    if (tid == 0) g_bsum[blockIdx.x] = ws[31];
}

__global__ void scan_block_kernel() {   // 1 block, 128 threads >= 98 partials
    __shared__ int wsum[4];
    int t = threadIdx.x, lane = t & 31, wid = t >> 5;
    int v = (t < SCAN_NBLK) ? g_bsum[t] : 0;
    int x = v;
    #pragma unroll
    for (int o = 1; o < 32; o <<= 1) {
        int y = __shfl_up_sync(0xFFFFFFFFu, x, o);
        if (lane >= o) x += y;
    }
    if (lane == 31) wsum[wid] = x;
    __syncthreads();
    if (t == 0) {
        int a = 0;
        #pragma unroll
        for (int k = 0; k < 4; k++) { int s = wsum[k]; wsum[k] = a; a += s; }
    }
    __syncthreads();
    int excl = wsum[wid] + x - v;
    if (t < SCAN_NBLK) g_bsum[t] = excl;
}

__global__ void scan_add_kernel() {
    int i = blockIdx.x * blockDim.x + threadIdx.x;
    if (i < NN) {
        int r = g_rowptr[i] + g_bsum[i >> 10];
        g_rowptr[i] = r;
        g_cursor[i] = r;
    }
    if (i == 0) g_rowptr[NN] = EE;
}

__global__ void fill_csr_kernel(const int* __restrict__ src, const int* __restrict__ dst) {
    int e = blockIdx.x * blockDim.x + threadIdx.x;
    if (e < EE) {
        int s = src[e], d = dst[e];
        int slot = atomicAdd(&g_cursor[d], 1);
        float w = g_dinv[s] * g_dinv[d];
        g_edge[slot] = make_int2(s, __float_as_int(w));
    }
}

// ================= fp16-split mma.sync GEMM =================
// C[N,BN] = A[N,128] @ W[128,BN], fp32-grade: x = hi + lo (fp16 each),
// D = Ah*Bh + Ah*Bl + Al*Bh accumulated in fp32 by HMMA.16816.
__device__ __forceinline__ uint32_t s2u(const void* p) {
    uint32_t a;
    asm("{ .reg .u64 t; cvta.to.shared.u64 t, %1; cvt.u32.u64 %0, t; }" : "=r"(a) : "l"(p));
    return a;
}

#define LDSM4(r, a)                                                            \
    asm volatile("ldmatrix.sync.aligned.m8n8.x4.shared.b16 {%0,%1,%2,%3}, [%4];" \
                 : "=r"((r)[0]), "=r"((r)[1]), "=r"((r)[2]), "=r"((r)[3])      \
                 : "r"(a))

__device__ __forceinline__ void mma16816(float* c, const uint32_t* a, const uint32_t* b) {
    asm volatile(
        "mma.sync.aligned.m16n8k16.row.col.f32.f16.f16.f32 "
        "{%0,%1,%2,%3}, {%4,%5,%6,%7}, {%8,%9}, {%0,%1,%2,%3};"
        : "+f"(c[0]), "+f"(c[1]), "+f"(c[2]), "+f"(c[3])
        : "r"(a[0]), "r"(a[1]), "r"(a[2]), "r"(a[3]), "r"(b[0]), "r"(b[1]));
}

__device__ __forceinline__ uint32_t pack2(__half a, __half b) {
    __half2 h = __halves2half2(a, b);
    return *(uint32_t*)&h;
}

// smem tile: rows of KC=64 fp16 + 8 pad halves (row stride 72 halves = 144 B)
template <int BN>
__global__ void __launch_bounds__(256, 2)
gemm_mma_kernel(const float* __restrict__ A, const float* __restrict__ W,
                float* __restrict__ C) {
    constexpr int K = 128, KC = 64, RS = 72;
    constexpr int A_HI = 0;
    constexpr int A_LO = 128 * RS;
    constexpr int B_HI = 2 * 128 * RS;
    constexpr int B_LO = B_HI + BN * RS;
    constexpr int NT = BN / 16;          // n8-tiles per warp (8 or 4)
    constexpr int NP = NT / 2;           // ldmatrix x4 pairs (4 or 2)

    extern __shared__ __half sm[];
    const uint32_t sb = s2u(sm);
    const int tid  = threadIdx.x;
    const int lane = tid & 31;
    const int warp = tid >> 5;
    const int wm = (warp & 3) * 32;
    const int wn = (warp >> 2) * (BN / 2);
    const int rowBase = blockIdx.x * 128;

    float acc[2][NT][4];
    #pragma unroll
    for (int mt = 0; mt < 2; mt++)
        #pragma unroll
        for (int nt = 0; nt < NT; nt++)
            #pragma unroll
            for (int q = 0; q < 4; q++) acc[mt][nt][q] = 0.0f;

    // ldmatrix lane->address maps
    const int aRow = (lane & 7) + ((lane >> 3) & 1) * 8;
    const int aK   = (lane >> 4) * 8;
    const int bN   = (lane & 7) + ((lane >> 4) << 3);
    const int bK   = ((lane >> 3) & 1) * 8;

    for (int kc = 0; kc < 2; kc++) {
        // ---- stage A chunk (128 x 64 fp32 -> hi/lo fp16) ----
        #pragma unroll
        for (int l = 0; l < 8; l++) {
            int i = tid + l * 256;           // 2048 float4
            int r = i >> 4;
            int c = (i & 15) * 4;
            float4 v = make_float4(0.f, 0.f, 0.f, 0.f);
            int gr = rowBase + r;
            if (gr < NN) v = *(const float4*)(A + (size_t)gr * K + kc * KC + c);
            __half h0 = __float2half_rn(v.x), h1 = __float2half_rn(v.y);
            __half h2 = __float2half_rn(v.z), h3 = __float2half_rn(v.w);
            __half q0 = __float2half_rn(v.x - __half2float(h0));
            __half q1 = __float2half_rn(v.y - __half2float(h1));
            __half q2 = __float2half_rn(v.z - __half2float(h2));
            __half q3 = __float2half_rn(v.w - __half2float(h3));
            *(uint2*)&sm[A_HI + r * RS + c] = make_uint2(pack2(h0, h1), pack2(h2, h3));
            *(uint2*)&sm[A_LO + r * RS + c] = make_uint2(pack2(q0, q1), pack2(q2, q3));
        }
        // ---- stage B chunk: Bsm[n][k] = W[kc*64+k][n] ----
        #pragma unroll
        for (int l = 0; l < BN * KC / 4 / 256; l++) {
            int i  = tid + l * 256;
            int n  = i % BN;
            int k0 = (i / BN) * 4;
            float v0 = W[(size_t)(kc * KC + k0 + 0) * BN + n];
            float v1 = W[(size_t)(kc * KC + k0 + 1) * BN + n];
            float v2 = W[(size_t)(kc * KC + k0 + 2) * BN + n];
            float v3 = W[(size_t)(kc * KC + k0 + 3) * BN + n];
            __half h0 = __float2half_rn(v0), h1 = __float2half_rn(v1);
            __half h2 = __float2half_rn(v2), h3 = __float2half_rn(v3);
            __half q0 = __float2half_rn(v0 - __half2float(h0));
            __half q1 = __float2half_rn(v1 - __half2float(h1));
            __half q2 = __float2half_rn(v2 - __half2float(h2));
            __half q3 = __float2half_rn(v3 - __half2float(h3));
            *(uint2*)&sm[B_HI + n * RS + k0] = make_uint2(pack2(h0, h1), pack2(h2, h3));
            *(uint2*)&sm[B_LO + n * RS + k0] = make_uint2(pack2(q0, q1), pack2(q2, q3));
        }
        __syncthreads();

        #pragma unroll
        for (int ks = 0; ks < KC / 16; ks++) {
            uint32_t ah[2][4], al[2][4];
            #pragma unroll
            for (int mt = 0; mt < 2; mt++) {
                uint32_t off = (uint32_t)((wm + mt * 16 + aRow) * RS + ks * 16 + aK) * 2;
                LDSM4(ah[mt], sb + A_HI * 2 + off);
                LDSM4(al[mt], sb + A_LO * 2 + off);
            }
            #pragma unroll
            for (int np = 0; np < NP; np++) {
                uint32_t bh[4], bl[4];
                uint32_t off = (uint32_t)((wn + np * 16 + bN) * RS + ks * 16 + bK) * 2;
                LDSM4(bh, sb + B_HI * 2 + off);
                LDSM4(bl, sb + B_LO * 2 + off);
                #pragma unroll
                for (int mt = 0; mt < 2; mt++) {
                    mma16816(acc[mt][np * 2 + 0], ah[mt], &bh[0]);
                    mma16816(acc[mt][np * 2 + 0], ah[mt], &bl[0]);
                    mma16816(acc[mt][np * 2 + 0], al[mt], &bh[0]);
                    mma16816(acc[mt][np * 2 + 1], ah[mt], &bh[2]);
                    mma16816(acc[mt][np * 2 + 1], ah[mt], &bl[2]);
                    mma16816(acc[mt][np * 2 + 1], al[mt], &bh[2]);
                }
            }
        }
        __syncthreads();
    }

    const int g  = lane >> 2;
    const int tg = lane & 3;
    #pragma unroll
    for (int mt = 0; mt < 2; mt++) {
        int r0 = rowBase + wm + mt * 16 + g;
        #pragma unroll
        for (int nt = 0; nt < NT; nt++) {
            int col = wn + nt * 8 + tg * 2;
            if (r0 < NN)
                *(float2*)(C + (size_t)r0 * BN + col) = make_float2(acc[mt][nt][0], acc[mt][nt][1]);
            if (r0 + 8 < NN)
                *(float2*)(C + (size_t)(r0 + 8) * BN + col) = make_float2(acc[mt][nt][2], acc[mt][nt][3]);
        }
    }
}

// ---------------- Aggregation: warp per destination node (gather) ----------------
template <int D, bool RELU>
__global__ void agg_kernel(const float* __restrict__ hW,
                           const float* __restrict__ bias,
                           float* __restrict__ out) {
    constexpr int V = D / 32;                 // floats per lane (4 or 2)
    int gw   = (blockIdx.x * blockDim.x + threadIdx.x) >> 5;
    int lane = threadIdx.x & 31;
    if (gw >= NN) return;

    float di = g_dinv[gw];
    float acc[V];
    {   // self loop: weight = dinv^2
        float w = di * di;
        const float* p = hW + (size_t)gw * D + lane * V;
        if (V == 4) {
            float4 r = *(const float4*)p;
            acc[0] = w * r.x; acc[1] = w * r.y; acc[2] = w * r.z; acc[3] = w * r.w;
        } else {
            float2 r = *(const float2*)p;
            acc[0] = w * r.x; acc[1] = w * r.y;
        }
    }
    int j   = g_rowptr[gw];
    int end = g_rowptr[gw + 1];
    // unroll-4: four independent gathers in flight
    for (; j + 4 <= end; j += 4) {
        int2 e0 = g_edge[j],     e1 = g_edge[j + 1];
        int2 e2 = g_edge[j + 2], e3 = g_edge[j + 3];
        float w0 = __int_as_float(e0.y), w1 = __int_as_float(e1.y);
        float w2 = __int_as_float(e2.y), w3 = __int_as_float(e3.y);
        if (V == 4) {
            float4 r0 = *(const float4*)(hW + (size_t)e0.x * D + lane * 4);
            float4 r1 = *(const float4*)(hW + (size_t)e1.x * D + lane * 4);
            float4 r2 = *(const float4*)(hW + (size_t)e2.x * D + lane * 4);
            float4 r3 = *(const float4*)(hW + (size_t)e3.x * D + lane * 4);
            acc[0] += w0 * r0.x; acc[1] += w0 * r0.y; acc[2] += w0 * r0.z; acc[3] += w0 * r0.w;
            acc[0] += w1 * r1.x; acc[1] += w1 * r1.y; acc[2] += w1 * r1.z; acc[3] += w1 * r1.w;
            acc[0] += w2 * r2.x; acc[1] += w2 * r2.y; acc[2] += w2 * r2.z; acc[3] += w2 * r2.w;
            acc[0] += w3 * r3.x; acc[1] += w3 * r3.y; acc[2] += w3 * r3.z; acc[3] += w3 * r3.w;
        } else {
            float2 r0 = *(const float2*)(hW + (size_t)e0.x * D + lane * 2);
            float2 r1 = *(const float2*)(hW + (size_t)e1.x * D + lane * 2);
            float2 r2 = *(const float2*)(hW + (size_t)e2.x * D + lane * 2);
            float2 r3 = *(const float2*)(hW + (size_t)e3.x * D + lane * 2);
            acc[0] += w0 * r0.x; acc[1] += w0 * r0.y;
            acc[0] += w1 * r1.x; acc[1] += w1 * r1.y;
            acc[0] += w2 * r2.x; acc[1] += w2 * r2.y;
            acc[0] += w3 * r3.x; acc[1] += w3 * r3.y;
        }
    }
    for (; j < end; j++) {
        int2 e = g_edge[j];
        float w = __int_as_float(e.y);
        if (V == 4) {
            float4 r = *(const float4*)(hW + (size_t)e.x * D + lane * 4);
            acc[0] += w * r.x; acc[1] += w * r.y; acc[2] += w * r.z; acc[3] += w * r.w;
        } else {
            float2 r = *(const float2*)(hW + (size_t)e.x * D + lane * 2);
            acc[0] += w * r.x; acc[1] += w * r.y;
        }
    }
    float* po = out + (size_t)gw * D + lane * V;
    if (V == 4) {
        float4 b = *(const float4*)(bias + lane * 4);
        float4 o;
        o.x = acc[0] + b.x; o.y = acc[1] + b.y; o.z = acc[2] + b.z; o.w = acc[3] + b.w;
        if (RELU) {
            o.x = fmaxf(o.x, 0.f); o.y = fmaxf(o.y, 0.f);
            o.z = fmaxf(o.z, 0.f); o.w = fmaxf(o.w, 0.f);
        }
        *(float4*)po = o;
    } else {
        float2 b = *(const float2*)(bias + lane * 2);
        float2 o;
        o.x = acc[0] + b.x; o.y = acc[1] + b.y;
        if (RELU) { o.x = fmaxf(o.x, 0.f); o.y = fmaxf(o.y, 0.f); }
        *(float2*)po = o;
    }
}

// ---------------- launch ----------------
extern "C" void kernel_launch(void* const* d_in, const int* in_sizes, int n_in,
                              void* d_out, int out_size) {
    const float* x  = (const float*)d_in[0];
    const float* W0 = (const float*)d_in[1];
    const float* b0 = (const float*)d_in[2];
    const float* W1 = (const float*)d_in[3];
    const float* b1 = (const float*)d_in[4];
    const float* W2 = (const float*)d_in[5];
    const float* b2 = (const float*)d_in[6];
    const int*  src = (const int*)d_in[7];
    const int*  dst = (const int*)d_in[8];
    float* out = (float*)d_out;

    float *bufA = nullptr, *bufB = nullptr;
    void* degp = nullptr;
    cudaGetSymbolAddress((void**)&bufA, g_bufA);
    cudaGetSymbolAddress((void**)&bufB, g_bufB);
    cudaGetSymbolAddress(&degp, g_deg);

    // one-time host-side infra (streams/events are host objects, not device mem)
    static cudaStream_t sB = nullptr;
    static cudaEvent_t evFork = nullptr, evBuild = nullptr;
    if (sB == nullptr) {
        cudaStreamCreateWithFlags(&sB, cudaStreamNonBlocking);
        cudaEventCreateWithFlags(&evFork, cudaEventDisableTiming);
        cudaEventCreateWithFlags(&evBuild, cudaEventDisableTiming);
    }

    const int SMEM128 = (2 * 128 + 2 * 128) * 72 * 2;   // 73728
    const int SMEM64  = (2 * 128 + 2 * 64)  * 72 * 2;   // 55296
    cudaFuncSetAttribute(gemm_mma_kernel<128>,
                         cudaFuncAttributeMaxDynamicSharedMemorySize, SMEM128);
    cudaFuncSetAttribute(gemm_mma_kernel<64>,
                         cudaFuncAttributeMaxDynamicSharedMemorySize, SMEM64);

    const int TPB = 256;
    const int edgeBlocks = (EE + TPB - 1) / TPB;
    const int gemmBlocks = (NN + 127) / 128;
    const int aggBlocks  = (NN * 32 + TPB - 1) / TPB;  // warp per node

    // ---- fork: CSR build on sB, concurrent with gemm0 on the main stream ----
    cudaEventRecord(evFork, 0);
    cudaStreamWaitEvent(sB, evFork, 0);

    cudaMemsetAsync(degp, 0, NN * sizeof(int), sB);
    count_deg_kernel<<<edgeBlocks, TPB, 0, sB>>>(dst);
    scan_local_kernel<<<SCAN_NBLK, SCAN_TPB, 0, sB>>>();
    scan_block_kernel<<<1, 128, 0, sB>>>();
    scan_add_kernel<<<(NN + 1023) / 1024, 1024, 0, sB>>>();
    fill_csr_kernel<<<edgeBlocks, TPB, 0, sB>>>(src, dst);
    cudaEventRecord(evBuild, sB);

    // gemm0 runs concurrently with the build
    gemm_mma_kernel<128><<<gemmBlocks, TPB, SMEM128>>>(x, W0, bufA);

    // join: agg0 needs both gemm0 (main stream order) and the CSR (evBuild)
    cudaStreamWaitEvent(0, evBuild, 0);

    agg_kernel<128, true><<<aggBlocks, TPB>>>(bufA, b0, bufB);
    // layer 1
    gemm_mma_kernel<128><<<gemmBlocks, TPB, SMEM128>>>(bufB, W1, bufA);
    agg_kernel<128, true><<<aggBlocks, TPB>>>(bufA, b1, bufB);
    // layer 2 (no relu) -> d_out
    gemm_mma_kernel<64><<<gemmBlocks, TPB, SMEM64>>>(bufB, W2, bufA);
    agg_kernel<64, false><<<aggBlocks, TPB>>>(bufA, b2, out);
}

// round 11
// speedup vs baseline: 1.0699x; 1.0039x over previous
#include <cuda_runtime.h>
#include <cuda_fp16.h>
#include <cstdint>
#include <cstddef>

#define NN   100000
#define EE   1600000
#define DINC 128
#define DHC  128
#define DOUTC 64

// ---------------- scratch (no allocations allowed) ----------------
__device__ int   g_deg[NN];
__device__ float g_dinv[NN];
__device__ int   g_rowptr[NN + 1];
__device__ int   g_cursor[NN];
__device__ int2  g_edge[EE];                     // {src, wgt-bits}, grouped by dst
__device__ float g_hbuf[(size_t)NN * DHC];       // fp32 hidden (gemm input)
__device__ __align__(16) short g_qtab[(size_t)NN * DHC];  // int16 gather table
__device__ float g_scl[NN];                      // per-row dequant scale

#define SCAN_TPB 1024
#define SCAN_NBLK ((NN + SCAN_TPB - 1) / SCAN_TPB)   // 98
__device__ int g_bsum[128];

// ---------------- graph build ----------------
__global__ void count_deg_kernel(const int* __restrict__ dst) {
    int e = blockIdx.x * blockDim.x + threadIdx.x;
    if (e < EE) atomicAdd(&g_deg[dst[e]], 1);
}

__global__ void scan_local_kernel() {
    __shared__ int ws[32];
    int tid  = threadIdx.x;
    int lane = tid & 31;
    int wid  = tid >> 5;
    int i = blockIdx.x * SCAN_TPB + tid;
    int v = (i < NN) ? g_deg[i] : 0;
    if (i < NN) g_dinv[i] = rsqrtf((float)(v + 1));   // +1 self loop
    int x = v;
    #pragma unroll
    for (int o = 1; o < 32; o <<= 1) {
        int y = __shfl_up_sync(0xFFFFFFFFu, x, o);
        if (lane >= o) x += y;
    }
    if (lane == 31) ws[wid] = x;
    __syncthreads();
    if (wid == 0) {
        int s = ws[lane];
        #pragma unroll
        for (int o = 1; o < 32; o <<= 1) {
            int y = __shfl_up_sync(0xFFFFFFFFu, s, o);
            if (lane >= o) s += y;
        }
        ws[lane] = s;
    }
    __syncthreads();
    int excl = (wid ? ws[wid - 1] : 0) + x - v;
    if (i < NN) g_rowptr[i] = excl;
    if (tid == 0) g_bsum[blockIdx.x] = ws[31];
}

__global__ void scan_block_kernel() {
    __shared__ int wsum[4];
    int t = threadIdx.x, lane = t & 31, wid = t >> 5;
    int v = (t < SCAN_NBLK) ? g_bsum[t] : 0;
    int x = v;
    #pragma unroll
    for (int o = 1; o < 32; o <<= 1) {
        int y = __shfl_up_sync(0xFFFFFFFFu, x, o);
        if (lane >= o) x += y;
    }
    if (lane == 31) wsum[wid] = x;
    __syncthreads();
    if (t == 0) {
        int a = 0;
        #pragma unroll
        for (int k = 0; k < 4; k++) { int s = wsum[k]; wsum[k] = a; a += s; }
    }
    __syncthreads();
    int excl = wsum[wid] + x - v;
    if (t < SCAN_NBLK) g_bsum[t] = excl;
}

__global__ void scan_add_kernel() {
    int i = blockIdx.x * blockDim.x + threadIdx.x;
    if (i < NN) {
        int r = g_rowptr[i] + g_bsum[i >> 10];
        g_rowptr[i] = r;
        g_cursor[i] = r;
    }
    if (i == 0) g_rowptr[NN] = EE;
}

__global__ void fill_csr_kernel(const int* __restrict__ src, const int* __restrict__ dst) {
    int e = blockIdx.x * blockDim.x + threadIdx.x;
    if (e < EE) {
        int s = src[e], d = dst[e];
        int slot = atomicAdd(&g_cursor[d], 1);
        float w = g_dinv[s] * g_dinv[d];
        g_edge[slot] = make_int2(s, __float_as_int(w));
    }
}

// ================= fp16-split mma.sync GEMM + int16-quant epilogue =================
__device__ __forceinline__ uint32_t s2u(const void* p) {
    uint32_t a;
    asm("{ .reg .u64 t; cvta.to.shared.u64 t, %1; cvt.u32.u64 %0, t; }" : "=r"(a) : "l"(p));
    return a;
}

#define LDSM4(r, a)                                                            \
    asm volatile("ldmatrix.sync.aligned.m8n8.x4.shared.b16 {%0,%1,%2,%3}, [%4];" \
                 : "=r"((r)[0]), "=r"((r)[1]), "=r"((r)[2]), "=r"((r)[3])      \
                 : "r"(a))

__device__ __forceinline__ void mma16816(float* c, const uint32_t* a, const uint32_t* b) {
    asm volatile(
        "mma.sync.aligned.m16n8k16.row.col.f32.f16.f16.f32 "
        "{%0,%1,%2,%3}, {%4,%5,%6,%7}, {%8,%9}, {%0,%1,%2,%3};"
        : "+f"(c[0]), "+f"(c[1]), "+f"(c[2]), "+f"(c[3])
        : "r"(a[0]), "r"(a[1]), "r"(a[2]), "r"(a[3]), "r"(b[0]), "r"(b[1]));
}

__device__ __forceinline__ uint32_t pack2(__half a, __half b) {
    __half2 h = __halves2half2(a, b);
    return *(uint32_t*)&h;
}

__device__ __forceinline__ short q16(float v, float inv) {
    int q = __float2int_rn(v * inv);
    q = max(-32767, min(32767, q));
    return (short)q;
}

template <int BN>
__global__ void __launch_bounds__(256, 2)
gemm_mma_kernel(const float* __restrict__ A, const float* __restrict__ W,
                short* __restrict__ QT, float* __restrict__ SCL) {
    constexpr int K = 128, KC = 64, RS = 72;
    constexpr int A_HI = 0;
    constexpr int A_LO = 128 * RS;
    constexpr int B_HI = 2 * 128 * RS;
    constexpr int B_LO = B_HI + BN * RS;
    constexpr int NT = BN / 16;
    constexpr int NP = NT / 2;

    extern __shared__ __half sm[];
    const uint32_t sb = s2u(sm);
    const int tid  = threadIdx.x;
    const int lane = tid & 31;
    const int warp = tid >> 5;
    const int wm = (warp & 3) * 32;
    const int wn = (warp >> 2) * (BN / 2);
    const int rowBase = blockIdx.x * 128;

    float acc[2][NT][4];
    #pragma unroll
    for (int mt = 0; mt < 2; mt++)
        #pragma unroll
        for (int nt = 0; nt < NT; nt++)
            #pragma unroll
            for (int q = 0; q < 4; q++) acc[mt][nt][q] = 0.0f;

    const int aRow = (lane & 7) + ((lane >> 3) & 1) * 8;
    const int aK   = (lane >> 4) * 8;
    const int bN   = (lane & 7) + ((lane >> 4) << 3);
    const int bK   = ((lane >> 3) & 1) * 8;

    for (int kc = 0; kc < 2; kc++) {
        #pragma unroll
        for (int l = 0; l < 8; l++) {
            int i = tid + l * 256;
            int r = i >> 4;
            int c = (i & 15) * 4;
            float4 v = make_float4(0.f, 0.f, 0.f, 0.f);
            int gr = rowBase + r;
            if (gr < NN) v = *(const float4*)(A + (size_t)gr * K + kc * KC + c);
            __half h0 = __float2half_rn(v.x), h1 = __float2half_rn(v.y);
            __half h2 = __float2half_rn(v.z), h3 = __float2half_rn(v.w);
            __half q0 = __float2half_rn(v.x - __half2float(h0));
            __half q1 = __float2half_rn(v.y - __half2float(h1));
            __half q2 = __float2half_rn(v.z - __half2float(h2));
            __half q3 = __float2half_rn(v.w - __half2float(h3));
            *(uint2*)&sm[A_HI + r * RS + c] = make_uint2(pack2(h0, h1), pack2(h2, h3));
            *(uint2*)&sm[A_LO + r * RS + c] = make_uint2(pack2(q0, q1), pack2(q2, q3));
        }
        #pragma unroll
        for (int l = 0; l < BN * KC / 4 / 256; l++) {
            int i  = tid + l * 256;
            int n  = i % BN;
            int k0 = (i / BN) * 4;
            float v0 = W[(size_t)(kc * KC + k0 + 0) * BN + n];
            float v1 = W[(size_t)(kc * KC + k0 + 1) * BN + n];
            float v2 = W[(size_t)(kc * KC + k0 + 2) * BN + n];
            float v3 = W[(size_t)(kc * KC + k0 + 3) * BN + n];
            __half h0 = __float2half_rn(v0), h1 = __float2half_rn(v1);
            __half h2 = __float2half_rn(v2), h3 = __float2half_rn(v3);
            __half q0 = __float2half_rn(v0 - __half2float(h0));
            __half q1 = __float2half_rn(v1 - __half2float(h1));
            __half q2 = __float2half_rn(v2 - __half2float(h2));
            __half q3 = __float2half_rn(v3 - __half2float(h3));
            *(uint2*)&sm[B_HI + n * RS + k0] = make_uint2(pack2(h0, h1), pack2(h2, h3));
            *(uint2*)&sm[B_LO + n * RS + k0] = make_uint2(pack2(q0, q1), pack2(q2, q3));
        }
        __syncthreads();

        #pragma unroll
        for (int ks = 0; ks < KC / 16; ks++) {
            uint32_t ah[2][4], al[2][4];
            #pragma unroll
            for (int mt = 0; mt < 2; mt++) {
                uint32_t off = (uint32_t)((wm + mt * 16 + aRow) * RS + ks * 16 + aK) * 2;
                LDSM4(ah[mt], sb + A_HI * 2 + off);
                LDSM4(al[mt], sb + A_LO * 2 + off);
            }
            #pragma unroll
            for (int np = 0; np < NP; np++) {
                uint32_t bh[4], bl[4];
                uint32_t off = (uint32_t)((wn + np * 16 + bN) * RS + ks * 16 + bK) * 2;
                LDSM4(bh, sb + B_HI * 2 + off);
                LDSM4(bl, sb + B_LO * 2 + off);
                #pragma unroll
                for (int mt = 0; mt < 2; mt++) {
                    mma16816(acc[mt][np * 2 + 0], ah[mt], &bh[0]);
                    mma16816(acc[mt][np * 2 + 0], ah[mt], &bl[0]);
                    mma16816(acc[mt][np * 2 + 0], al[mt], &bh[0]);
                    mma16816(acc[mt][np * 2 + 1], ah[mt], &bh[2]);
                    mma16816(acc[mt][np * 2 + 1], ah[mt], &bl[2]);
                    mma16816(acc[mt][np * 2 + 1], al[mt], &bh[2]);
                }
            }
        }
        __syncthreads();
    }

    // ---- epilogue: rowwise absmax -> int16 quantize ----
    const int g  = lane >> 2;
    const int tg = lane & 3;
    const int wHalf = warp >> 2;              // which N-half this warp holds
    float* redmax = (float*)sm;               // [2][128], smem reused after sync

    float pm[2][2];
    #pragma unroll
    for (int mt = 0; mt < 2; mt++) {
        float m0 = 0.f, m1 = 0.f;
        #pragma unroll
        for (int nt = 0; nt < NT; nt++) {
            m0 = fmaxf(m0, fmaxf(fabsf(acc[mt][nt][0]), fabsf(acc[mt][nt][1])));
            m1 = fmaxf(m1, fmaxf(fabsf(acc[mt][nt][2]), fabsf(acc[mt][nt][3])));
        }
        #pragma unroll
        for (int o = 1; o <= 2; o <<= 1) {
            m0 = fmaxf(m0, __shfl_xor_sync(0xFFFFFFFFu, m0, o));
            m1 = fmaxf(m1, __shfl_xor_sync(0xFFFFFFFFu, m1, o));
        }
        pm[mt][0] = m0; pm[mt][1] = m1;
    }
    if (tg == 0) {
        #pragma unroll
        for (int mt = 0; mt < 2; mt++) {
            redmax[wHalf * 128 + wm + mt * 16 + g]     = pm[mt][0];
            redmax[wHalf * 128 + wm + mt * 16 + g + 8] = pm[mt][1];
        }
    }
    __syncthreads();

    #pragma unroll
    for (int mt = 0; mt < 2; mt++) {
        #pragma unroll
        for (int h = 0; h < 2; h++) {
            int r  = wm + mt * 16 + g + h * 8;
            int gr = rowBase + r;
            float fm  = fmaxf(redmax[r], redmax[128 + r]);
            float inv = (fm > 0.f) ? 32766.0f / fm : 0.0f;
            if (gr < NN) {
                if (wHalf == 0 && tg == 0) SCL[gr] = fm * (1.0f / 32766.0f);
                #pragma unroll
                for (int nt = 0; nt < NT; nt++) {
                    int col = wn + nt * 8 + tg * 2;
                    short2 qq = make_short2(q16(acc[mt][nt][h * 2 + 0], inv),
                                            q16(acc[mt][nt][h * 2 + 1], inv));
                    *(short2*)&QT[(size_t)gr * BN + col] = qq;
                }
            }
        }
    }
}

// ---------------- Aggregation: warp per dst node, int16 dequant gather ----------------
template <int D, bool RELU>
__global__ void agg_kernel(const short* __restrict__ QT,
                           const float* __restrict__ SCL,
                           const float* __restrict__ bias,
                           float* __restrict__ out) {
    constexpr int V = D / 32;                 // int16s per lane (4 or 2)
    int gw   = (blockIdx.x * blockDim.x + threadIdx.x) >> 5;
    int lane = threadIdx.x & 31;
    if (gw >= NN) return;

    float di = g_dinv[gw];
    float acc[V];
    {   // self loop: weight = dinv^2
        float ws = di * di * SCL[gw];
        if (V == 4) {
            short4 q = *(const short4*)(QT + (size_t)gw * D + lane * 4);
            acc[0] = ws * (float)q.x; acc[1] = ws * (float)q.y;
            acc[2] = ws * (float)q.z; acc[3] = ws * (float)q.w;
        } else {
            short2 q = *(const short2*)(QT + (size_t)gw * D + lane * 2);
            acc[0] = ws * (float)q.x; acc[1] = ws * (float)q.y;
        }
    }
    int j   = g_rowptr[gw];
    int end = g_rowptr[gw + 1];
    for (; j + 2 <= end; j += 2) {
        int2 e0 = g_edge[j], e1 = g_edge[j + 1];
        float ws0 = __int_as_float(e0.y) * SCL[e0.x];
        float ws1 = __int_as_float(e1.y) * SCL[e1.x];
        if (V == 4) {
            short4 q0 = *(const short4*)(QT + (size_t)e0.x * D + lane * 4);
            short4 q1 = *(const short4*)(QT + (size_t)e1.x * D + lane * 4);
            acc[0] += ws0 * (float)q0.x; acc[1] += ws0 * (float)q0.y;
            acc[2] += ws0 * (float)q0.z; acc[3] += ws0 * (float)q0.w;
            acc[0] += ws1 * (float)q1.x; acc[1] += ws1 * (float)q1.y;
            acc[2] += ws1 * (float)q1.z; acc[3] += ws1 * (float)q1.w;
        } else {
            short2 q0 = *(const short2*)(QT + (size_t)e0.x * D + lane * 2);
            short2 q1 = *(const short2*)(QT + (size_t)e1.x * D + lane * 2);
            acc[0] += ws0 * (float)q0.x; acc[1] += ws0 * (float)q0.y;
            acc[0] += ws1 * (float)q1.x; acc[1] += ws1 * (float)q1.y;
        }
    }
    if (j < end) {
        int2 e = g_edge[j];
        float ws = __int_as_float(e.y) * SCL[e.x];
        if (V == 4) {
            short4 q = *(const short4*)(QT + (size_t)e.x * D + lane * 4);
            acc[0] += ws * (float)q.x; acc[1] += ws * (float)q.y;
            acc[2] += ws * (float)q.z; acc[3] += ws * (float)q.w;
        } else {
            short2 q = *(const short2*)(QT + (size_t)e.x * D + lane * 2);
            acc[0] += ws * (float)q.x; acc[1] += ws * (float)q.y;
        }
    }
    float* po = out + (size_t)gw * D + lane * V;
    if (V == 4) {
        float4 b = *(const float4*)(bias + lane * 4);
        float4 o;
        o.x = acc[0] + b.x; o.y = acc[1] + b.y; o.z = acc[2] + b.z; o.w = acc[3] + b.w;
        if (RELU) {
            o.x = fmaxf(o.x, 0.f); o.y = fmaxf(o.y, 0.f);
            o.z = fmaxf(o.z, 0.f); o.w = fmaxf(o.w, 0.f);
        }
        *(float4*)po = o;
    } else {
        float2 b = *(const float2*)(bias + lane * 2);
        float2 o;
        o.x = acc[0] + b.x; o.y = acc[1] + b.y;
        if (RELU) { o.x = fmaxf(o.x, 0.f); o.y = fmaxf(o.y, 0.f); }
        *(float2*)po = o;
    }
}

// ---------------- launch ----------------
extern "C" void kernel_launch(void* const* d_in, const int* in_sizes, int n_in,
                              void* d_out, int out_size) {
    const float* x  = (const float*)d_in[0];
    const float* W0 = (const float*)d_in[1];
    const float* b0 = (const float*)d_in[2];
    const float* W1 = (const float*)d_in[3];
    const float* b1 = (const float*)d_in[4];
    const float* W2 = (const float*)d_in[5];
    const float* b2 = (const float*)d_in[6];
    const int*  src = (const int*)d_in[7];
    const int*  dst = (const int*)d_in[8];
    float* out = (float*)d_out;

    float *hbuf = nullptr, *scl = nullptr;
    short* qtab = nullptr;
    void* degp = nullptr;
    cudaGetSymbolAddress((void**)&hbuf, g_hbuf);
    cudaGetSymbolAddress((void**)&scl, g_scl);
    cudaGetSymbolAddress((void**)&qtab, g_qtab);
    cudaGetSymbolAddress(&degp, g_deg);

    static cudaStream_t sB = nullptr;
    static cudaEvent_t evFork = nullptr, evBuild = nullptr;
    if (sB == nullptr) {
        cudaStreamCreateWithFlags(&sB, cudaStreamNonBlocking);
        cudaEventCreateWithFlags(&evFork, cudaEventDisableTiming);
        cudaEventCreateWithFlags(&evBuild, cudaEventDisableTiming);
    }

    const int SMEM128 = (2 * 128 + 2 * 128) * 72 * 2;   // 73728
    const int SMEM64  = (2 * 128 + 2 * 64)  * 72 * 2;   // 55296
    cudaFuncSetAttribute(gemm_mma_kernel<128>,
                         cudaFuncAttributeMaxDynamicSharedMemorySize, SMEM128);
    cudaFuncSetAttribute(gemm_mma_kernel<64>,
                         cudaFuncAttributeMaxDynamicSharedMemorySize, SMEM64);

    const int TPB = 256;
    const int edgeBlocks = (EE + TPB - 1) / TPB;
    const int gemmBlocks = (NN + 127) / 128;
    const int aggBlocks  = (NN * 32 + TPB - 1) / TPB;

    // ---- fork: CSR build on sB, concurrent with gemm0 ----
    cudaEventRecord(evFork, 0);
    cudaStreamWaitEvent(sB, evFork, 0);

    cudaMemsetAsync(degp, 0, NN * sizeof(int), sB);
    count_deg_kernel<<<edgeBlocks, TPB, 0, sB>>>(dst);
    scan_local_kernel<<<SCAN_NBLK, SCAN_TPB, 0, sB>>>();
    scan_block_kernel<<<1, 128, 0, sB>>>();
    scan_add_kernel<<<(NN + 1023) / 1024, 1024, 0, sB>>>();
    fill_csr_kernel<<<edgeBlocks, TPB, 0, sB>>>(src, dst);
    cudaEventRecord(evBuild, sB);

    gemm_mma_kernel<128><<<gemmBlocks, TPB, SMEM128>>>(x, W0, qtab, scl);

    cudaStreamWaitEvent(0, evBuild, 0);

    agg_kernel<128, true><<<aggBlocks, TPB>>>(qtab, scl, b0, hbuf);
    gemm_mma_kernel<128><<<gemmBlocks, TPB, SMEM128>>>(hbuf, W1, qtab, scl);
    agg_kernel<128, true><<<aggBlocks, TPB>>>(qtab, scl, b1, hbuf);
    gemm_mma_kernel<64><<<gemmBlocks, TPB, SMEM64>>>(hbuf, W2, qtab, scl);
    agg_kernel<64, false><<<aggBlocks, TPB>>>(qtab, scl, b2, out);
}